// round 11
// baseline (speedup 1.0000x reference)
#include <cuda_runtime.h>
#include <cuda_fp16.h>
#include <cstdint>

// ----------------------------------------------------------------------------
// out[M,N] = (A[M,K]_f32 @ W[N,K]_int8^T) * scale[N] + bias[N]
// M=8192, K=4096, N=11008.
// Weight arrives as INT32 (harness materializes int8 as int32) -> int4 reads.
// compute_103 (no 'a') => no tcgen05. Legacy mma.sync pipe measured at
// rt~8 cyc/HMMA(f32 acc) => GEMM floor ~1.2ms; goal = tensor busy 63%->85%.
// R11: warp 64x64 (low crossbar) + THREE CTAs/SM (3 warps/SMSP):
//   BK=32, 3 stages => 60KB smem/CTA; regs<=168 via launch_bounds(128,3),
//   in-loop fragments (no double buffer; cross-CTA overlap hides latency).
// ----------------------------------------------------------------------------

static constexpr int MDIM = 8192;
static constexpr int KDIM = 4096;
static constexpr int NDIM = 11008;

static constexpr int BM = 128;
static constexpr int BN = 128;
static constexpr int BK = 32;                   // halfs per K-chunk
static constexpr int STAGES = 3;
static constexpr int KITERS = KDIM / BK;        // 128

static constexpr int ROW_BYTES = 80;            // 32 halfs (64B) + 16B pad
static constexpr int A_STAGE_BYTES = BM * ROW_BYTES;              // 10240
static constexpr int B_STAGE_BYTES = BN * ROW_BYTES;              // 10240
static constexpr int STAGE_BYTES = A_STAGE_BYTES + B_STAGE_BYTES; // 20480
static constexpr int SMEM_BYTES = STAGES * STAGE_BYTES;           // 61440

static constexpr int MTILES = MDIM / BM;        // 64
static constexpr int NTILES = NDIM / BN;        // 86
static constexpr int THREADS = 128;             // 4 warps: 2 in M x 2 in N

// fp16 scratch (device globals: no runtime allocation)
__device__ __half g_A[(size_t)MDIM * KDIM];     // 64 MiB
__device__ __half g_B[(size_t)NDIM * KDIM];     // 86 MiB

// ----------------------------------------------------------------------------
// helpers
// ----------------------------------------------------------------------------
__device__ __forceinline__ uint32_t smem_to_u32(const void* p) {
    uint32_t a;
    asm("{ .reg .u64 t; cvta.to.shared.u64 t, %1; cvt.u32.u64 %0, t; }"
        : "=r"(a) : "l"(p));
    return a;
}

#define CP_ASYNC_16(dst_u32, src_ptr) \
    asm volatile("cp.async.cg.shared.global [%0], [%1], 16;" \
                 :: "r"(dst_u32), "l"(src_ptr) : "memory")

#define CP_ASYNC_COMMIT() \
    asm volatile("cp.async.commit_group;" ::: "memory")

#define CP_ASYNC_WAIT_GROUP(n) \
    asm volatile("cp.async.wait_group %0;" :: "n"(n) : "memory")

__device__ __forceinline__ void ldsm_x4(uint32_t* r, uint32_t addr) {
    asm volatile("ldmatrix.sync.aligned.m8n8.x4.shared.b16 {%0,%1,%2,%3}, [%4];"
                 : "=r"(r[0]), "=r"(r[1]), "=r"(r[2]), "=r"(r[3])
                 : "r"(addr));
}

__device__ __forceinline__ void mma16816(float* d, const uint32_t* a, const uint32_t* b) {
    asm volatile(
        "mma.sync.aligned.m16n8k16.row.col.f32.f16.f16.f32 "
        "{%0,%1,%2,%3}, {%4,%5,%6,%7}, {%8,%9}, {%0,%1,%2,%3};"
        : "+f"(d[0]), "+f"(d[1]), "+f"(d[2]), "+f"(d[3])
        : "r"(a[0]), "r"(a[1]), "r"(a[2]), "r"(a[3]), "r"(b[0]), "r"(b[1]));
}

// ----------------------------------------------------------------------------
// merged convert: fp32 input -> fp16 AND int32 weight -> fp16 (one launch)
// ----------------------------------------------------------------------------
static constexpr int N_IN4 = MDIM * KDIM / 4;   // 8388608
static constexpr int N_W4  = NDIM * KDIM / 4;   // 11272192

__global__ void k_cvt(const float4* __restrict__ in, const int4* __restrict__ w) {
    const int i = blockIdx.x * blockDim.x + threadIdx.x;   // exact grid sizing
    if (i < N_IN4) {
        float4 v = in[i];
        __half2 h0 = __floats2half2_rn(v.x, v.y);
        __half2 h1 = __floats2half2_rn(v.z, v.w);
        uint2 u;
        u.x = *reinterpret_cast<uint32_t*>(&h0);
        u.y = *reinterpret_cast<uint32_t*>(&h1);
        reinterpret_cast<uint2*>(g_A)[i] = u;
    } else {
        const int j = i - N_IN4;
        int4 wv = w[j];                                    // int32 in [-128,127]
        __half2 h0 = __floats2half2_rn((float)wv.x, (float)wv.y);
        __half2 h1 = __floats2half2_rn((float)wv.z, (float)wv.w);
        uint2 u;
        u.x = *reinterpret_cast<uint32_t*>(&h0);
        u.y = *reinterpret_cast<uint32_t*>(&h1);
        reinterpret_cast<uint2*>(g_B)[j] = u;
    }
}

// ----------------------------------------------------------------------------
// GEMM: CTA 128x128, 4 warps (2Mx2N, warp 64x64), BK=32, 3 stages, occ=3
// ----------------------------------------------------------------------------
__global__ void __launch_bounds__(THREADS, 3)
k_gemm(const float* __restrict__ scale, const float* __restrict__ bias,
       float* __restrict__ out)
{
    extern __shared__ char smem[];
    const uint32_t sb = smem_to_u32(smem);

    const int tid  = threadIdx.x;
    const int wid  = tid >> 5;
    const int lane = tid & 31;

    const int ntile = blockIdx.x % NTILES;
    const int mtile = blockIdx.x / NTILES;
    const int m0 = mtile * BM;
    const int n0 = ntile * BN;

    const int wm = (wid & 1) * 64;     // warp M offset (2 warps in M)
    const int wn = (wid >> 1) * 64;    // warp N offset (2 warps in N)

    // producer: one K-chunk (32 halfs/row) into stage s — 8 LDGSTS / thread
    auto load_stage = [&](int s, int kt) {
        const __half* Ag = g_A + (size_t)m0 * KDIM + (size_t)kt * BK;
        const __half* Bg = g_B + (size_t)n0 * KDIM + (size_t)kt * BK;
        const uint32_t abase = sb + s * STAGE_BYTES;
        const uint32_t bbase = abase + A_STAGE_BYTES;
        #pragma unroll
        for (int j = 0; j < 4; j++) {              // A: 128 rows x 4 x 16B
            const int idx = tid + j * THREADS;     // 0..511
            const int row = idx >> 2;
            const int c   = idx & 3;
            CP_ASYNC_16(abase + row * ROW_BYTES + c * 16,
                        (const char*)(Ag + (size_t)row * KDIM) + c * 16);
        }
        #pragma unroll
        for (int j = 0; j < 4; j++) {              // B: 128 rows x 4 x 16B
            const int idx = tid + j * THREADS;
            const int row = idx >> 2;
            const int c   = idx & 3;
            CP_ASYNC_16(bbase + row * ROW_BYTES + c * 16,
                        (const char*)(Bg + (size_t)row * KDIM) + c * 16);
        }
    };

    // prologue: fill STAGES-1 stages
    #pragma unroll
    for (int s = 0; s < STAGES - 1; s++) {
        load_stage(s, s);
        CP_ASYNC_COMMIT();
    }

    float acc[4][8][4];
    #pragma unroll
    for (int mi = 0; mi < 4; mi++)
        #pragma unroll
        for (int ni = 0; ni < 8; ni++)
            #pragma unroll
            for (int r = 0; r < 4; r++) acc[mi][ni][r] = 0.0f;

    // ldmatrix lane addressing
    const int a_row_in = lane & 15;
    const int a_koff   = (lane >> 4) * 8;
    const int b_n_in   = ((lane >> 4) << 3) + (lane & 7);
    const int b_koff   = ((lane >> 3) & 1) * 8;

    // mainloop (128 iters of K=32)
    int s = 0;                          // stage index = k % 3
    for (int k = 0; k < KITERS; k++) {
        CP_ASYNC_WAIT_GROUP(STAGES - 2);   // chunk k resident (this thread)
        __syncthreads();                   // visible CTA-wide

        const uint32_t abase = sb + s * STAGE_BYTES;
        const uint32_t bbase = abase + A_STAGE_BYTES;

        #pragma unroll
        for (int kk = 0; kk < 2; kk++) {   // 2 x k16 per 32-chunk
            const int kb = kk * 16;
            uint32_t af[4][4];
            uint32_t bf[4][4];
            #pragma unroll
            for (int p = 0; p < 4; p++) {
                const int nrow = wn + p * 16 + b_n_in;
                ldsm_x4(bf[p], bbase + nrow * ROW_BYTES + (kb + b_koff) * 2);
            }
            #pragma unroll
            for (int mi = 0; mi < 4; mi++) {
                const int row = wm + mi * 16 + a_row_in;
                ldsm_x4(af[mi], abase + row * ROW_BYTES + (kb + a_koff) * 2);
            }
            // next-stage global issue tucked behind kk=0's frag-load latency
            if (kk == 0 && k + STAGES - 1 < KITERS) {
                load_stage((s + STAGES - 1) % STAGES, k + STAGES - 1);
                CP_ASYNC_COMMIT();
            }
            #pragma unroll
            for (int mi = 0; mi < 4; mi++)
                #pragma unroll
                for (int ni = 0; ni < 8; ni++)
                    mma16816(acc[mi][ni], af[mi], &bf[ni >> 1][(ni & 1) * 2]);
        }
        s = (s + 1 == STAGES) ? 0 : s + 1;
    }

    // epilogue: fused scale+bias, direct float2 stores
    float2 sc2[8], bi2[8];
    #pragma unroll
    for (int ni = 0; ni < 8; ni++) {
        const int col = n0 + wn + ni * 8 + (lane & 3) * 2;
        sc2[ni] = *reinterpret_cast<const float2*>(scale + col);
        bi2[ni] = *reinterpret_cast<const float2*>(bias + col);
    }

    #pragma unroll
    for (int mi = 0; mi < 4; mi++) {
        const int row0 = m0 + wm + mi * 16 + (lane >> 2);
        #pragma unroll
        for (int ni = 0; ni < 8; ni++) {
            const int col = n0 + wn + ni * 8 + (lane & 3) * 2;
            float2 v0, v1;
            v0.x = fmaf(acc[mi][ni][0], sc2[ni].x, bi2[ni].x);
            v0.y = fmaf(acc[mi][ni][1], sc2[ni].y, bi2[ni].y);
            v1.x = fmaf(acc[mi][ni][2], sc2[ni].x, bi2[ni].x);
            v1.y = fmaf(acc[mi][ni][3], sc2[ni].y, bi2[ni].y);
            *reinterpret_cast<float2*>(out + (size_t)row0 * NDIM + col) = v0;
            *reinterpret_cast<float2*>(out + (size_t)(row0 + 8) * NDIM + col) = v1;
        }
    }
}

// ----------------------------------------------------------------------------
// launch
// ----------------------------------------------------------------------------
extern "C" void kernel_launch(void* const* d_in, const int* in_sizes, int n_in,
                              void* d_out, int out_size)
{
    const float* input  = (const float*)d_in[0];   // [4,2048,4096] f32
    const int4*  weight = (const int4*)d_in[1];    // [11008,4096] int8-as-int32
    const float* scale  = (const float*)d_in[2];   // [11008] f32
    const float* bias   = (const float*)d_in[3];   // [1,11008] f32
    float* out = (float*)d_out;

    (void)in_sizes; (void)n_in; (void)out_size;

    k_cvt<<<(N_IN4 + N_W4) / 256, 256>>>((const float4*)input, weight);

    cudaFuncSetAttribute(k_gemm, cudaFuncAttributeMaxDynamicSharedMemorySize,
                         SMEM_BYTES);
    k_gemm<<<MTILES * NTILES, THREADS, SMEM_BYTES>>>(scale, bias, out);
}

// round 12
// speedup vs baseline: 1.0992x; 1.0992x over previous
#include <cuda_runtime.h>
#include <cuda_fp16.h>
#include <cstdint>

// ----------------------------------------------------------------------------
// out[M,N] = (A[M,K]_f32 @ W[N,K]_int8^T) * scale[N] + bias[N]
// M=8192, K=4096, N=11008.
// Weight arrives as INT32 (harness materializes int8 as int32) -> int4 reads.
// compute_103 (no 'a') => no tcgen05. Legacy mma.sync (HMMA, f32 acc, rt~7-8).
// R12 = R8 config (best: 1845us; CTA 128x128, 8 warps 64x32, BK=64, 3 stages,
// occ 2 => 4 warps/SMSP) + bubble removal:
//   - B fragments FIRST, then A: first MMA ready after 3 ldsm, not 6
//   - cp.async issue tucked in kk=0 ldsm shadow
//   - merged convert kernel
// ----------------------------------------------------------------------------

static constexpr int MDIM = 8192;
static constexpr int KDIM = 4096;
static constexpr int NDIM = 11008;

static constexpr int BM = 128;
static constexpr int BN = 128;
static constexpr int BK = 64;                   // halfs per K-chunk
static constexpr int STAGES = 3;
static constexpr int KITERS = KDIM / BK;        // 64

static constexpr int ROW_BYTES = 144;           // 64 halfs + 16B pad
static constexpr int A_STAGE_BYTES = BM * ROW_BYTES;              // 18432
static constexpr int B_STAGE_BYTES = BN * ROW_BYTES;              // 18432
static constexpr int STAGE_BYTES = A_STAGE_BYTES + B_STAGE_BYTES; // 36864
static constexpr int SMEM_BYTES = STAGES * STAGE_BYTES;           // 110592

static constexpr int MTILES = MDIM / BM;        // 64
static constexpr int NTILES = NDIM / BN;        // 86
static constexpr int THREADS = 256;             // 8 warps: 2 in M x 4 in N

// fp16 scratch (device globals: no runtime allocation)
__device__ __half g_A[(size_t)MDIM * KDIM];     // 64 MiB
__device__ __half g_B[(size_t)NDIM * KDIM];     // 86 MiB

// ----------------------------------------------------------------------------
// helpers
// ----------------------------------------------------------------------------
__device__ __forceinline__ uint32_t smem_to_u32(const void* p) {
    uint32_t a;
    asm("{ .reg .u64 t; cvta.to.shared.u64 t, %1; cvt.u32.u64 %0, t; }"
        : "=r"(a) : "l"(p));
    return a;
}

#define CP_ASYNC_16(dst_u32, src_ptr) \
    asm volatile("cp.async.cg.shared.global [%0], [%1], 16;" \
                 :: "r"(dst_u32), "l"(src_ptr) : "memory")

#define CP_ASYNC_COMMIT() \
    asm volatile("cp.async.commit_group;" ::: "memory")

#define CP_ASYNC_WAIT_GROUP(n) \
    asm volatile("cp.async.wait_group %0;" :: "n"(n) : "memory")

__device__ __forceinline__ void ldsm_x4(uint32_t* r, uint32_t addr) {
    asm volatile("ldmatrix.sync.aligned.m8n8.x4.shared.b16 {%0,%1,%2,%3}, [%4];"
                 : "=r"(r[0]), "=r"(r[1]), "=r"(r[2]), "=r"(r[3])
                 : "r"(addr));
}

__device__ __forceinline__ void mma16816(float* d, const uint32_t* a, const uint32_t* b) {
    asm("mma.sync.aligned.m16n8k16.row.col.f32.f16.f16.f32 "
        "{%0,%1,%2,%3}, {%4,%5,%6,%7}, {%8,%9}, {%0,%1,%2,%3};"
        : "+f"(d[0]), "+f"(d[1]), "+f"(d[2]), "+f"(d[3])
        : "r"(a[0]), "r"(a[1]), "r"(a[2]), "r"(a[3]), "r"(b[0]), "r"(b[1]));
}

// ----------------------------------------------------------------------------
// merged convert: fp32 input -> fp16 AND int32 weight -> fp16 (one launch)
// ----------------------------------------------------------------------------
static constexpr int N_IN4 = MDIM * KDIM / 4;   // 8388608
static constexpr int N_W4  = NDIM * KDIM / 4;   // 11272192

__global__ void k_cvt(const float4* __restrict__ in, const int4* __restrict__ w) {
    const int i = blockIdx.x * blockDim.x + threadIdx.x;   // exact grid sizing
    if (i < N_IN4) {
        float4 v = in[i];
        __half2 h0 = __floats2half2_rn(v.x, v.y);
        __half2 h1 = __floats2half2_rn(v.z, v.w);
        uint2 u;
        u.x = *reinterpret_cast<uint32_t*>(&h0);
        u.y = *reinterpret_cast<uint32_t*>(&h1);
        reinterpret_cast<uint2*>(g_A)[i] = u;
    } else {
        const int j = i - N_IN4;
        int4 wv = w[j];                                    // int32 in [-128,127]
        __half2 h0 = __floats2half2_rn((float)wv.x, (float)wv.y);
        __half2 h1 = __floats2half2_rn((float)wv.z, (float)wv.w);
        uint2 u;
        u.x = *reinterpret_cast<uint32_t*>(&h0);
        u.y = *reinterpret_cast<uint32_t*>(&h1);
        reinterpret_cast<uint2*>(g_B)[j] = u;
    }
}

// ----------------------------------------------------------------------------
// GEMM: CTA 128x128, 8 warps (2Mx4N, warp 64x32), BK=64, 3 stages, occ=2
// ----------------------------------------------------------------------------
__global__ void __launch_bounds__(THREADS, 2)
k_gemm(const float* __restrict__ scale, const float* __restrict__ bias,
       float* __restrict__ out)
{
    extern __shared__ char smem[];
    const uint32_t sb = smem_to_u32(smem);

    const int tid  = threadIdx.x;
    const int wid  = tid >> 5;
    const int lane = tid & 31;

    const int ntile = blockIdx.x % NTILES;
    const int mtile = blockIdx.x / NTILES;
    const int m0 = mtile * BM;
    const int n0 = ntile * BN;

    const int wm = (wid & 1) * 64;     // warp M offset (2 warps in M)
    const int wn = (wid >> 1) * 32;    // warp N offset (4 warps in N)

    // producer: one K-chunk into stage s (8 cp.async per thread)
    auto load_stage = [&](int s, int kt) {
        const __half* Ag = g_A + (size_t)m0 * KDIM + (size_t)kt * BK;
        const __half* Bg = g_B + (size_t)n0 * KDIM + (size_t)kt * BK;
        const uint32_t abase = sb + s * STAGE_BYTES;
        const uint32_t bbase = abase + A_STAGE_BYTES;
        #pragma unroll
        for (int j = 0; j < 4; j++) {              // A: 128 rows x 8 x 16B
            const int idx = tid + j * THREADS;
            const int row = idx >> 3;
            const int c   = idx & 7;
            CP_ASYNC_16(abase + row * ROW_BYTES + c * 16,
                        (const char*)(Ag + (size_t)row * KDIM) + c * 16);
        }
        #pragma unroll
        for (int j = 0; j < 4; j++) {              // B: 128 rows x 8 x 16B
            const int idx = tid + j * THREADS;
            const int row = idx >> 3;
            const int c   = idx & 7;
            CP_ASYNC_16(bbase + row * ROW_BYTES + c * 16,
                        (const char*)(Bg + (size_t)row * KDIM) + c * 16);
        }
    };

    // prologue: fill STAGES-1 stages
    #pragma unroll
    for (int s = 0; s < STAGES - 1; s++) {
        load_stage(s, s);
        CP_ASYNC_COMMIT();
    }

    float acc[4][4][4];
    #pragma unroll
    for (int mi = 0; mi < 4; mi++)
        #pragma unroll
        for (int ni = 0; ni < 4; ni++)
            #pragma unroll
            for (int r = 0; r < 4; r++) acc[mi][ni][r] = 0.0f;

    // ldmatrix lane addressing
    const int a_row_in = lane & 15;
    const int a_koff   = (lane >> 4) * 8;
    const int b_n_in   = ((lane >> 4) << 3) + (lane & 7);
    const int b_koff   = ((lane >> 3) & 1) * 8;

    // mainloop
    for (int k = 0; k < KITERS; k++) {
        CP_ASYNC_WAIT_GROUP(STAGES - 2);   // chunk k resident (this thread)
        __syncthreads();                   // visible CTA-wide

        const uint32_t abase = sb + (k % STAGES) * STAGE_BYTES;
        const uint32_t bbase = abase + A_STAGE_BYTES;

        #pragma unroll
        for (int kk = 0; kk < 4; kk++) {
            const int kb = kk * 16;
            uint32_t af[4][4];
            uint32_t bf[2][4];
            // B first (2 ldsm), then A: first MMA (mi=0) needs bf* + af[0]
            // => ready after 3 ldsm instead of 6; af[1..3] hide under MMAs.
            #pragma unroll
            for (int p = 0; p < 2; p++) {
                const int nrow = wn + p * 16 + b_n_in;
                ldsm_x4(bf[p], bbase + nrow * ROW_BYTES + (kb + b_koff) * 2);
            }
            #pragma unroll
            for (int mi = 0; mi < 4; mi++) {
                const int row = wm + mi * 16 + a_row_in;
                ldsm_x4(af[mi], abase + row * ROW_BYTES + (kb + a_koff) * 2);
            }
            // next-stage global issue in the ldsm latency shadow of kk=0
            if (kk == 0) {
                if (k + STAGES - 1 < KITERS)
                    load_stage((k + STAGES - 1) % STAGES, k + STAGES - 1);
                CP_ASYNC_COMMIT();
            }
            #pragma unroll
            for (int mi = 0; mi < 4; mi++)
                #pragma unroll
                for (int ni = 0; ni < 4; ni++)
                    mma16816(acc[mi][ni], af[mi], &bf[ni >> 1][(ni & 1) * 2]);
        }
    }

    // epilogue: fused scale+bias, direct float2 stores
    float2 sc2[4], bi2[4];
    #pragma unroll
    for (int ni = 0; ni < 4; ni++) {
        const int col = n0 + wn + ni * 8 + (lane & 3) * 2;
        sc2[ni] = *reinterpret_cast<const float2*>(scale + col);
        bi2[ni] = *reinterpret_cast<const float2*>(bias + col);
    }

    #pragma unroll
    for (int mi = 0; mi < 4; mi++) {
        const int row0 = m0 + wm + mi * 16 + (lane >> 2);
        #pragma unroll
        for (int ni = 0; ni < 4; ni++) {
            const int col = n0 + wn + ni * 8 + (lane & 3) * 2;
            float2 v0, v1;
            v0.x = fmaf(acc[mi][ni][0], sc2[ni].x, bi2[ni].x);
            v0.y = fmaf(acc[mi][ni][1], sc2[ni].y, bi2[ni].y);
            v1.x = fmaf(acc[mi][ni][2], sc2[ni].x, bi2[ni].x);
            v1.y = fmaf(acc[mi][ni][3], sc2[ni].y, bi2[ni].y);
            *reinterpret_cast<float2*>(out + (size_t)row0 * NDIM + col) = v0;
            *reinterpret_cast<float2*>(out + (size_t)(row0 + 8) * NDIM + col) = v1;
        }
    }
}

// ----------------------------------------------------------------------------
// launch
// ----------------------------------------------------------------------------
extern "C" void kernel_launch(void* const* d_in, const int* in_sizes, int n_in,
                              void* d_out, int out_size)
{
    const float* input  = (const float*)d_in[0];   // [4,2048,4096] f32
    const int4*  weight = (const int4*)d_in[1];    // [11008,4096] int8-as-int32
    const float* scale  = (const float*)d_in[2];   // [11008] f32
    const float* bias   = (const float*)d_in[3];   // [1,11008] f32
    float* out = (float*)d_out;

    (void)in_sizes; (void)n_in; (void)out_size;

    k_cvt<<<(N_IN4 + N_W4) / 256, 256>>>((const float4*)input, weight);

    cudaFuncSetAttribute(k_gemm, cudaFuncAttributeMaxDynamicSharedMemorySize,
                         SMEM_BYTES);
    k_gemm<<<MTILES * NTILES, THREADS, SMEM_BYTES>>>(scale, bias, out);
}